// round 1
// baseline (speedup 1.0000x reference)
#include <cuda_runtime.h>
#include <cuda_bf16.h>

// Scalar double accumulator in device global memory (no allocations allowed).
__device__ double g_acc;

__global__ void init_kernel() {
    g_acc = 0.0;
}

// One block per row. Row-major x[B][N], target t = targets[row]:
// contribution of element (row, j) = softplus(x) - x * (j < t).
__global__ __launch_bounds__(256) void bce_kernel(
    const float* __restrict__ x,
    const long long* __restrict__ targets,
    int N)
{
    const int row = blockIdx.x;
    const long long t = targets[row];
    const float4* __restrict__ xr =
        reinterpret_cast<const float4*>(x + (size_t)row * N);
    const int n4 = N >> 2;

    float s = 0.0f;
    for (int i = threadIdx.x; i < n4; i += blockDim.x) {
        float4 v = xr[i];
        const long long c = (long long)i * 4;

        // stable softplus: max(x,0) + log(1 + exp(-|x|))
        float sp0 = fmaxf(v.x, 0.0f) + __logf(1.0f + __expf(-fabsf(v.x)));
        float sp1 = fmaxf(v.y, 0.0f) + __logf(1.0f + __expf(-fabsf(v.y)));
        float sp2 = fmaxf(v.z, 0.0f) + __logf(1.0f + __expf(-fabsf(v.z)));
        float sp3 = fmaxf(v.w, 0.0f) + __logf(1.0f + __expf(-fabsf(v.w)));

        float sub = 0.0f;
        if (c + 0 < t) sub += v.x;
        if (c + 1 < t) sub += v.y;
        if (c + 2 < t) sub += v.z;
        if (c + 3 < t) sub += v.w;

        s += (sp0 + sp1) + (sp2 + sp3) - sub;
    }

    // Warp reduction
    #pragma unroll
    for (int o = 16; o > 0; o >>= 1)
        s += __shfl_xor_sync(0xFFFFFFFFu, s, o);

    __shared__ float warp_sums[8];
    const int lane = threadIdx.x & 31;
    const int wid  = threadIdx.x >> 5;
    if (lane == 0) warp_sums[wid] = s;
    __syncthreads();

    if (threadIdx.x < 32) {
        float v = (lane < 8) ? warp_sums[lane] : 0.0f;
        #pragma unroll
        for (int o = 4; o > 0; o >>= 1)
            v += __shfl_xor_sync(0xFFFFFFFFu, v, o);
        if (lane == 0)
            atomicAdd(&g_acc, (double)v);
    }
}

__global__ void finalize_kernel(float* out, double inv_count) {
    out[0] = (float)(g_acc * inv_count);
}

extern "C" void kernel_launch(void* const* d_in, const int* in_sizes, int n_in,
                              void* d_out, int out_size)
{
    const float*     x  = (const float*)d_in[0];
    const long long* tg = (const long long*)d_in[1];
    float* out = (float*)d_out;

    const int B = in_sizes[1];          // 8192 rows (one target per row)
    const int N = in_sizes[0] / B;      // 8192 cols

    init_kernel<<<1, 1>>>();
    bce_kernel<<<B, 256>>>(x, tg, N);
    finalize_kernel<<<1, 1>>>(out, 1.0 / ((double)B * (double)N));
}